// round 5
// baseline (speedup 1.0000x reference)
#include <cuda_runtime.h>
#include <cstdint>

// Correlation layer: out[b, di*21+dj, h, w] = (1/64) * sum_c f1[b,c,h,w] * f2pad[b,c,h+di,w+dj]
// B=4, C=64, H=W=128, MAX_DISP=10, KS=21 (441 displacements), fp32.

#define B_      4
#define C_      64
#define H_      128
#define W_      128
#define KS_     21
#define PAD_    10

#define HB   4      // h rows per CTA
#define DIB  3      // di values per CTA
#define CC   8      // channels per chunk
#define NCHUNK (C_ / CC)   // 8
#define PW   152    // padded f2 row width
#define NROW (HB + DIB - 1)  // 6

#define F1_STRIDE (CC * W_ + 4)   // 1028 floats (4112 B ≡ 16 mod 128)
#define F2_STRIDE (CC * PW + 4)   // 1220 floats (4880 B ≡ 16 mod 128)
#define SMEM_F1   (HB * F1_STRIDE)     // 4112 floats
#define SMEM_F2   (NROW * F2_STRIDE)   // 7320 floats
#define BUF_FLOATS (SMEM_F1 + SMEM_F2)
#define SMEM_BYTES (2 * BUF_FLOATS * 4)  // 91456 B

#define NTHREADS 384   // 12 warps = 4 hl * 3 dil; lanes = 8 wg * 4 sub

// ---------------- cp.async helpers ----------------
__device__ __forceinline__ void cp_async16(float* smem_dst, const float* gsrc) {
    uint32_t s = (uint32_t)__cvta_generic_to_shared(smem_dst);
    asm volatile("cp.async.cg.shared.global [%0], [%1], 16;\n" :: "r"(s), "l"(gsrc));
}
__device__ __forceinline__ void cp_async8(float* smem_dst, const float* gsrc) {
    uint32_t s = (uint32_t)__cvta_generic_to_shared(smem_dst);
    asm volatile("cp.async.ca.shared.global [%0], [%1], 8;\n" :: "r"(s), "l"(gsrc));
}
__device__ __forceinline__ void cp_commit() {
    asm volatile("cp.async.commit_group;\n" ::: "memory");
}
template <int N>
__device__ __forceinline__ void cp_wait() {
    asm volatile("cp.async.wait_group %0;\n" :: "n"(N) : "memory");
}

// ---------------- inner compute ----------------
// Thread covers dj = sub + 4k (k=0..5; k=5 meaningful only for sub==0, junk
// otherwise, never stored) and w in [w0, w0+16). fbw is the thread's f2 window
// pre-shifted by sub at load time, so all indexing is static (registers only).
// The 4 sub lanes per wg read identical fa addresses (4-way LDS broadcast);
// fbw scalar loads are conflict-free per quarter-warp.
__device__ __forceinline__ void compute_chunk(const float* __restrict__ f1p,
                                              const float* __restrict__ f2p,
                                              float (&acc)[6][16]) {
#pragma unroll
    for (int c = 0; c < CC; c++) {
        const float4* f1v = reinterpret_cast<const float4*>(f1p + c * W_);
        const float* f2r  = f2p + c * PW;
        float fa[16];
        float fbw[36];
#pragma unroll
        for (int i = 0; i < 4; i++) {
            float4 t = f1v[i];
            fa[4 * i + 0] = t.x; fa[4 * i + 1] = t.y;
            fa[4 * i + 2] = t.z; fa[4 * i + 3] = t.w;
        }
#pragma unroll
        for (int i = 0; i < 36; i++) fbw[i] = f2r[i];
#pragma unroll
        for (int k = 0; k < 5; k++) {
#pragma unroll
            for (int wi = 0; wi < 16; wi++)
                acc[k][wi] = fmaf(fa[wi], fbw[4 * k + wi], acc[k][wi]);
        }
        // row 5: dj = 20 for sub==0; junk accumulation for sub>=1 (not stored)
#pragma unroll
        for (int wi = 0; wi < 16; wi++)
            acc[5][wi] = fmaf(fa[wi], fbw[20 + wi], acc[5][wi]);
    }
}

// ---------------- staging (cp.async) ----------------
__device__ __forceinline__ void stage_chunk(const float* __restrict__ f1g,
                                            const float* __restrict__ f2g,
                                            float* f1b, float* f2b,
                                            int b, int cb, int h0, int r0,
                                            int rlo, int n2, int tid) {
    for (int i = tid; i < HB * CC * (W_ / 4); i += NTHREADS) {   // 1024 total
        int w4 = i & 31;
        int c  = (i >> 5) & (CC - 1);
        int h  = i >> 8;
        const float* src = f1g + ((size_t)(b * C_ + cb + c) * H_ + (h0 + h)) * W_ + w4 * 4;
        cp_async16(f1b + h * F1_STRIDE + c * W_ + w4 * 4, src);
    }
    for (int i = tid; i < n2; i += NTHREADS) {                   // up to 3072
        int x2 = i & 63;
        int c  = (i >> 6) & (CC - 1);
        int r  = rlo + (i >> 9);
        const float* src = f2g + ((size_t)(b * C_ + cb + c) * H_ + (r0 + r)) * W_ + x2 * 2;
        cp_async8(f2b + r * F2_STRIDE + c * PW + PAD_ + x2 * 2, src);
    }
}

extern __shared__ float smem[];

__global__ __launch_bounds__(NTHREADS, 1)
void corr_kernel(const float* __restrict__ f1g,
                 const float* __restrict__ f2g,
                 float* __restrict__ out) {
    const int tid  = threadIdx.x;
    const int warp = tid >> 5;
    const int lane = tid & 31;
    const int hl   = warp & 3;      // h row (warp-uniform)
    const int dil  = warp >> 2;     // local di (warp-uniform)
    const int wg   = lane >> 2;     // w tile
    const int sub  = lane & 3;      // dj mod 4 (4-way broadcast group)
    const int w0   = wg * 16;

    const int b   = blockIdx.z;
    const int h0  = blockIdx.y * HB;
    const int di0 = blockIdx.x * DIB;
    const int r0  = h0 + di0 - PAD_;

    int rlo = (r0 < 0) ? -r0 : 0;
    int rhi = (r0 + NROW > H_) ? (H_ - r0) : NROW;
    if (rhi < rlo) { rlo = 0; rhi = 0; }
    const int n2 = (rhi - rlo) * (CC * 64);

    float* buf0 = smem;
    float* buf1 = smem + BUF_FLOATS;

    // one-time zero of both f2 regions (padding + OOB rows stay zero forever)
    {
        float4 z = make_float4(0.f, 0.f, 0.f, 0.f);
        float4* z0 = reinterpret_cast<float4*>(buf0 + SMEM_F1);
        float4* z1 = reinterpret_cast<float4*>(buf1 + SMEM_F1);
        for (int i = tid; i < SMEM_F2 / 4; i += NTHREADS) { z0[i] = z; z1[i] = z; }
    }
    __syncthreads();

    stage_chunk(f1g, f2g, buf0, buf0 + SMEM_F1, b, 0 * CC, h0, r0, rlo, n2, tid);
    cp_commit();
    stage_chunk(f1g, f2g, buf1, buf1 + SMEM_F1, b, 1 * CC, h0, r0, rlo, n2, tid);
    cp_commit();

    float acc[6][16];
#pragma unroll
    for (int k = 0; k < 6; k++)
#pragma unroll
        for (int wi = 0; wi < 16; wi++) acc[k][wi] = 0.f;

    const int f1off = hl * F1_STRIDE + w0;
    const int f2off = SMEM_F1 + (hl + dil) * F2_STRIDE + w0 + sub;  // sub-shifted window

    for (int cc = 0; cc < NCHUNK; cc++) {
        float* buf = (cc & 1) ? buf1 : buf0;
        if (cc < NCHUNK - 1) cp_wait<1>(); else cp_wait<0>();
        __syncthreads();

        compute_chunk(buf + f1off, buf + f2off, acc);

        __syncthreads();
        if (cc + 2 < NCHUNK)
            stage_chunk(f1g, f2g, buf, buf + SMEM_F1, b, (cc + 2) * CC, h0, r0,
                        rlo, n2, tid);
        cp_commit();
    }

    // ---- epilogue: rows dj = sub + 4k ----
    const float inv = 1.0f / 64.0f;
    const int di = di0 + dil;
    const int h  = h0 + hl;
    const int nk = (sub == 0) ? 6 : 5;   // row 5 valid only for sub==0 (dj=20)
    for (int k = 0; k < nk; k++) {
        const int d = di * KS_ + sub + 4 * k;
        float* o = out + (((size_t)b * (KS_ * KS_) + d) * H_ + h) * W_ + w0;
#pragma unroll
        for (int i = 0; i < 4; i++) {
            float4 v = make_float4(acc[k][4 * i + 0] * inv,
                                   acc[k][4 * i + 1] * inv,
                                   acc[k][4 * i + 2] * inv,
                                   acc[k][4 * i + 3] * inv);
            *reinterpret_cast<float4*>(o + 4 * i) = v;
        }
    }
}

extern "C" void kernel_launch(void* const* d_in, const int* in_sizes, int n_in,
                              void* d_out, int out_size) {
    const float* f1 = (const float*)d_in[0];
    const float* f2 = (const float*)d_in[1];
    float* out = (float*)d_out;

    cudaFuncSetAttribute(corr_kernel, cudaFuncAttributeMaxDynamicSharedMemorySize,
                         SMEM_BYTES);

    dim3 grid(KS_ / DIB, H_ / HB, B_);   // (7, 32, 4) = 896 CTAs
    corr_kernel<<<grid, NTHREADS, SMEM_BYTES>>>(f1, f2, out);
}

// round 6
// speedup vs baseline: 1.5510x; 1.5510x over previous
#include <cuda_runtime.h>
#include <cstdint>

// Correlation layer: out[b, di*21+dj, h, w] = (1/64) * sum_c f1[b,c,h,w] * f2pad[b,c,h+di,w+dj]
// B=4, C=64, H=W=128, MAX_DISP=10, KS=21 (441 displacements), fp32.

#define B_      4
#define C_      64
#define H_      128
#define W_      128
#define KS_     21
#define PAD_    10

#define HB   4      // h rows per CTA
#define DIB  3      // di values per CTA
#define CC   8      // channels per chunk
#define NCHUNK (C_ / CC)   // 8
#define PW   152    // padded f2 row width
#define NROW (HB + DIB - 1)  // 6

#define F1_STRIDE (CC * W_ + 4)   // 1028 floats (4112 B ≡ 16 mod 128)
#define F2_STRIDE (CC * PW + 4)   // 1220 floats (4880 B ≡ 16 mod 128)
#define SMEM_F1   (HB * F1_STRIDE)       // 4112 floats
#define F2_COPY   (NROW * F2_STRIDE + 12) // 7332 floats: copy size padded so
                                          // copy1-copy0 = 29328 B ≡ 16 mod 128
#define BUF_FLOATS (SMEM_F1 + 2 * F2_COPY) // 18776 floats per buffer
#define SMEM_BYTES (2 * BUF_FLOATS * 4)    // 150208 B (double buffered)

#define NTHREADS 384   // 12 warps = 4 hl * 3 dil; lanes = 16 wg * 2 djp

// ---------------- cp.async helpers ----------------
__device__ __forceinline__ void cp_async16(float* smem_dst, const float* gsrc) {
    uint32_t s = (uint32_t)__cvta_generic_to_shared(smem_dst);
    asm volatile("cp.async.cg.shared.global [%0], [%1], 16;\n" :: "r"(s), "l"(gsrc));
}
__device__ __forceinline__ void cp_async8(float* smem_dst, const float* gsrc) {
    uint32_t s = (uint32_t)__cvta_generic_to_shared(smem_dst);
    asm volatile("cp.async.ca.shared.global [%0], [%1], 8;\n" :: "r"(s), "l"(gsrc));
}
__device__ __forceinline__ void cp_async4(float* smem_dst, const float* gsrc) {
    uint32_t s = (uint32_t)__cvta_generic_to_shared(smem_dst);
    asm volatile("cp.async.ca.shared.global [%0], [%1], 4;\n" :: "r"(s), "l"(gsrc));
}
__device__ __forceinline__ void cp_commit() {
    asm volatile("cp.async.commit_group;\n" ::: "memory");
}
template <int N>
__device__ __forceinline__ void cp_wait() {
    asm volatile("cp.async.wait_group %0;\n" :: "n"(N) : "memory");
}

// packed f32x2 fma: d = a*b + c on both 32-bit halves
__device__ __forceinline__ unsigned long long fma_x2(unsigned long long a,
                                                     unsigned long long b,
                                                     unsigned long long c) {
    unsigned long long d;
    asm("fma.rn.f32x2 %0, %1, %2, %3;" : "=l"(d) : "l"(a), "l"(b), "l"(c));
    return d;
}

// ---------------- inner compute ----------------
// Thread: dj = djp + 2k (k=0..10; k=10 junk for djp=1, never stored),
// w in [w0, w0+8). f2base points at copy_djp (copy1 is pre-shifted by one
// float), so both parities use identical even packed offsets: acc[k][p]
// needs fb packed pair at float offset 2(k+p) -> fb2[k+p].
__device__ __forceinline__ void compute_chunk(const float* __restrict__ f1p,
                                              const float* __restrict__ f2p,
                                              unsigned long long (&acc)[11][4]) {
#pragma unroll
    for (int c = 0; c < CC; c++) {
        const ulonglong2* f1v = reinterpret_cast<const ulonglong2*>(f1p + c * W_);
        const ulonglong2* f2v = reinterpret_cast<const ulonglong2*>(f2p + c * PW);
        unsigned long long fa2[4];
        unsigned long long fb2[14];
#pragma unroll
        for (int i = 0; i < 2; i++) {
            ulonglong2 t = f1v[i];
            fa2[2 * i] = t.x; fa2[2 * i + 1] = t.y;
        }
#pragma unroll
        for (int i = 0; i < 7; i++) {
            ulonglong2 t = f2v[i];
            fb2[2 * i] = t.x; fb2[2 * i + 1] = t.y;
        }
#pragma unroll
        for (int k = 0; k < 11; k++) {
#pragma unroll
            for (int p = 0; p < 4; p++)
                acc[k][p] = fma_x2(fa2[p], fb2[k + p], acc[k][p]);
        }
    }
}

// ---------------- staging (cp.async) ----------------
// f1: HB x CC x 128 floats (16B). copy0: interior x in [10,138) via 8B.
// copy1: copy1[9+x1] = row[x1], x1 in [0,128) via 4B (odd dst offset).
__device__ __forceinline__ void stage_chunk(const float* __restrict__ f1g,
                                            const float* __restrict__ f2g,
                                            float* buf,
                                            int b, int cb, int h0, int r0,
                                            int rlo, int nrows, int tid) {
    float* f1b = buf;
    float* c0  = buf + SMEM_F1;
    float* c1  = buf + SMEM_F1 + F2_COPY;

    for (int i = tid; i < HB * CC * (W_ / 4); i += NTHREADS) {   // 1024
        int w4 = i & 31;
        int c  = (i >> 5) & (CC - 1);
        int h  = i >> 8;
        const float* src = f1g + ((size_t)(b * C_ + cb + c) * H_ + (h0 + h)) * W_ + w4 * 4;
        cp_async16(f1b + h * F1_STRIDE + c * W_ + w4 * 4, src);
    }
    const int n2 = nrows * (CC * 64);
    for (int i = tid; i < n2; i += NTHREADS) {                   // <= 3072
        int x2 = i & 63;
        int c  = (i >> 6) & (CC - 1);
        int r  = rlo + (i >> 9);
        const float* src = f2g + ((size_t)(b * C_ + cb + c) * H_ + (r0 + r)) * W_ + x2 * 2;
        cp_async8(c0 + r * F2_STRIDE + c * PW + PAD_ + x2 * 2, src);
    }
    const int n1 = nrows * (CC * 128);
    for (int i = tid; i < n1; i += NTHREADS) {                   // <= 6144
        int x1 = i & 127;
        int c  = (i >> 7) & (CC - 1);
        int r  = rlo + (i >> 10);
        const float* src = f2g + ((size_t)(b * C_ + cb + c) * H_ + (r0 + r)) * W_ + x1;
        cp_async4(c1 + r * F2_STRIDE + c * PW + (PAD_ - 1) + x1, src);
    }
}

extern __shared__ float smem[];

__global__ __launch_bounds__(NTHREADS, 1)
void corr_kernel(const float* __restrict__ f1g,
                 const float* __restrict__ f2g,
                 float* __restrict__ out) {
    const int tid  = threadIdx.x;
    const int warp = tid >> 5;
    const int lane = tid & 31;
    const int hl   = warp & 3;      // h row (warp-uniform)
    const int dil  = warp >> 2;     // local di (warp-uniform)
    const int wg   = lane >> 1;     // w tile: w0 = wg*8
    const int djp  = lane & 1;      // dj parity
    const int w0   = wg * 8;

    const int b   = blockIdx.z;
    const int h0  = blockIdx.y * HB;
    const int di0 = blockIdx.x * DIB;
    const int r0  = h0 + di0 - PAD_;

    int rlo = (r0 < 0) ? -r0 : 0;
    int rhi = (r0 + NROW > H_) ? (H_ - r0) : NROW;
    if (rhi < rlo) { rlo = 0; rhi = 0; }
    const int nrows = rhi - rlo;

    float* buf0 = smem;
    float* buf1 = smem + BUF_FLOATS;

    // one-time zero of both f2 double-copies (padding/OOB stays zero forever)
    {
        float4 z = make_float4(0.f, 0.f, 0.f, 0.f);
        float4* z0 = reinterpret_cast<float4*>(buf0 + SMEM_F1);
        float4* z1 = reinterpret_cast<float4*>(buf1 + SMEM_F1);
        for (int i = tid; i < 2 * F2_COPY / 4; i += NTHREADS) { z0[i] = z; z1[i] = z; }
    }
    __syncthreads();

    stage_chunk(f1g, f2g, buf0, b, 0 * CC, h0, r0, rlo, nrows, tid);
    cp_commit();
    stage_chunk(f1g, f2g, buf1, b, 1 * CC, h0, r0, rlo, nrows, tid);
    cp_commit();

    unsigned long long acc[11][4];
#pragma unroll
    for (int k = 0; k < 11; k++)
#pragma unroll
        for (int p = 0; p < 4; p++) acc[k][p] = 0ull;

    const int f1off = hl * F1_STRIDE + w0;
    const int f2off = SMEM_F1 + djp * F2_COPY + (hl + dil) * F2_STRIDE + w0;

    for (int cc = 0; cc < NCHUNK; cc++) {
        float* buf = (cc & 1) ? buf1 : buf0;
        if (cc < NCHUNK - 1) cp_wait<1>(); else cp_wait<0>();
        __syncthreads();

        compute_chunk(buf + f1off, buf + f2off, acc);

        __syncthreads();
        if (cc + 2 < NCHUNK)
            stage_chunk(f1g, f2g, buf, b, (cc + 2) * CC, h0, r0, rlo, nrows, tid);
        cp_commit();
    }

    // ---- epilogue: rows dj = djp + 2k ----
    const float inv = 1.0f / 64.0f;
    const int di = di0 + dil;
    const int h  = h0 + hl;
    const int nk = (djp == 0) ? 11 : 10;   // dj=20 only exists for djp==0
    for (int k = 0; k < nk; k++) {
        const int d = di * KS_ + djp + 2 * k;
        float* o = out + (((size_t)b * (KS_ * KS_) + d) * H_ + h) * W_ + w0;
        float v[8];
#pragma unroll
        for (int p = 0; p < 4; p++) {
            float2 f = *reinterpret_cast<float2*>(&acc[k][p]);
            v[2 * p]     = f.x * inv;
            v[2 * p + 1] = f.y * inv;
        }
        *reinterpret_cast<float4*>(o)     = make_float4(v[0], v[1], v[2], v[3]);
        *reinterpret_cast<float4*>(o + 4) = make_float4(v[4], v[5], v[6], v[7]);
    }
}

extern "C" void kernel_launch(void* const* d_in, const int* in_sizes, int n_in,
                              void* d_out, int out_size) {
    const float* f1 = (const float*)d_in[0];
    const float* f2 = (const float*)d_in[1];
    float* out = (float*)d_out;

    cudaFuncSetAttribute(corr_kernel, cudaFuncAttributeMaxDynamicSharedMemorySize,
                         SMEM_BYTES);

    dim3 grid(KS_ / DIB, H_ / HB, B_);   // (7, 32, 4) = 896 CTAs
    corr_kernel<<<grid, NTHREADS, SMEM_BYTES>>>(f1, f2, out);
}

// round 7
// speedup vs baseline: 1.6367x; 1.0552x over previous
#include <cuda_runtime.h>
#include <cstdint>

// Correlation layer: out[b, di*21+dj, h, w] = (1/64) * sum_c f1[b,c,h,w] * f2pad[b,c,h+di,w+dj]
// B=4, C=64, H=W=128, MAX_DISP=10, KS=21 (441 displacements), fp32.

#define B_      4
#define C_      64
#define H_      128
#define W_      128
#define KS_     21
#define PAD_    10

#define HB   4      // h rows per CTA
#define DIB  3      // di values per CTA
#define CC   8      // channels per chunk
#define NCHUNK (C_ / CC)   // 8
#define PW   152    // padded f2 row width
#define NROW (HB + DIB - 1)  // 6

#define F1_STRIDE (CC * W_ + 4)   // 1028 floats (4112 B ≡ 16 mod 128)
#define F2_STRIDE (CC * PW + 4)   // 1220 floats (4880 B ≡ 16 mod 128)
#define SMEM_F1   (HB * F1_STRIDE)        // 4112 floats
#define F2_COPY   (NROW * F2_STRIDE + 12) // 7332 floats; copy1-copy0 = 29328 B ≡ 16 mod 128
#define F2_USED   (NROW * F2_STRIDE)      // 7320 floats actually addressed
#define BUF_FLOATS (SMEM_F1 + 2 * F2_COPY)
#define SMEM_BYTES (2 * BUF_FLOATS * 4)   // 150208 B

#define NTHREADS 384   // 12 warps = 4 hl * 3 dil; lanes = 16 wg * 2 djp

// ---------------- cp.async helpers ----------------
__device__ __forceinline__ void cp_async16(float* smem_dst, const float* gsrc) {
    uint32_t s = (uint32_t)__cvta_generic_to_shared(smem_dst);
    asm volatile("cp.async.cg.shared.global [%0], [%1], 16;\n" :: "r"(s), "l"(gsrc));
}
__device__ __forceinline__ void cp_async8(float* smem_dst, const float* gsrc) {
    uint32_t s = (uint32_t)__cvta_generic_to_shared(smem_dst);
    asm volatile("cp.async.ca.shared.global [%0], [%1], 8;\n" :: "r"(s), "l"(gsrc));
}
__device__ __forceinline__ void cp_commit() {
    asm volatile("cp.async.commit_group;\n" ::: "memory");
}
template <int N>
__device__ __forceinline__ void cp_wait() {
    asm volatile("cp.async.wait_group %0;\n" :: "n"(N) : "memory");
}

// packed f32x2 fma: d = a*b + c on both 32-bit halves
__device__ __forceinline__ unsigned long long fma_x2(unsigned long long a,
                                                     unsigned long long b,
                                                     unsigned long long c) {
    unsigned long long d;
    asm("fma.rn.f32x2 %0, %1, %2, %3;" : "=l"(d) : "l"(a), "l"(b), "l"(c));
    return d;
}

// ---------------- inner compute ----------------
// Thread: dj = djp + 2k (k=0..10; k=10 junk for djp=1, never stored),
// w in [w0, w0+8). f2p points at copy_djp; copy1 is c0 shifted by one float,
// so both parities read identical even packed offsets: fb2[k+p].
__device__ __forceinline__ void compute_chunk(const float* __restrict__ f1p,
                                              const float* __restrict__ f2p,
                                              unsigned long long (&acc)[11][4]) {
#pragma unroll
    for (int c = 0; c < CC; c++) {
        const ulonglong2* f1v = reinterpret_cast<const ulonglong2*>(f1p + c * W_);
        const ulonglong2* f2v = reinterpret_cast<const ulonglong2*>(f2p + c * PW);
        unsigned long long fa2[4];
        unsigned long long fb2[14];
#pragma unroll
        for (int i = 0; i < 2; i++) {
            ulonglong2 t = f1v[i];
            fa2[2 * i] = t.x; fa2[2 * i + 1] = t.y;
        }
#pragma unroll
        for (int i = 0; i < 7; i++) {
            ulonglong2 t = f2v[i];
            fb2[2 * i] = t.x; fb2[2 * i + 1] = t.y;
        }
#pragma unroll
        for (int k = 0; k < 11; k++) {
#pragma unroll
            for (int p = 0; p < 4; p++)
                acc[k][p] = fma_x2(fa2[p], fb2[k + p], acc[k][p]);
        }
    }
}

// ---------------- staging (cp.async, gmem -> smem) ----------------
// f1: HB x CC x 128 floats via 16B. c0: interior x in [10,138) via 8B.
// copy1 is NOT staged from gmem (built in smem afterwards).
// 384 ≡ 0 mod 64: per-thread x components are loop-invariant.
__device__ __forceinline__ void stage_chunk(const float* __restrict__ f1base,
                                            const float* __restrict__ f2base,
                                            float* buf,
                                            int rlo, int nrows, int tid) {
    // ---- f1: items i = h*256 + c*32 + w4, 1024 total ----
    {
        const int w4 = tid & 31;                // invariant
        int hc = tid >> 5;                      // h*8 + c, advances by 12
        float* f1b = buf + w4 * 4;
        const float* src0 = f1base + w4 * 4;
#pragma unroll
        for (int j = 0; j < 3; j++) {
            if (hc < HB * CC) {
                int h = hc >> 3, c = hc & 7;
                cp_async16(f1b + h * F1_STRIDE + c * W_,
                           src0 + c * (H_ * W_) + h * W_);
            }
            hc += 12;
        }
    }
    // ---- c0: items i = (r*8 + c)*64 + x2, nrows*512 total ----
    {
        const int x2 = tid & 63;                // invariant
        int rc = tid >> 6;                      // r*8 + c, advances by 6
        const int rcmax = nrows * 8;
        float* c0 = buf + SMEM_F1 + rlo * F2_STRIDE + PAD_ + x2 * 2;
        const float* src0 = f2base + rlo * W_ + x2 * 2;
#pragma unroll
        for (int j = 0; j < 8; j++) {
            if (rc < rcmax) {
                int r = rc >> 3, c = rc & 7;
                cp_async8(c0 + r * F2_STRIDE + c * PW,
                          src0 + c * (H_ * W_) + r * W_);
            }
            rc += 6;
        }
    }
}

// ---------------- copy1 build (smem -> smem 1-float shift) ----------------
// copy1[i] = c0[i+1]; covers all of F2_USED. Both c0 reads and copy1 writes
// are conflict-free 128b ops; the scalar pickup is a cheap 4-way wave.
__device__ __forceinline__ void build_copy1(float* buf, int tid) {
    const float* c0 = buf + SMEM_F1;
    float* c1 = buf + SMEM_F1 + F2_COPY;
#pragma unroll
    for (int j = 0; j < (F2_USED / 4 + NTHREADS - 1) / NTHREADS; j++) {  // 5 iters
        int i4 = (tid + j * NTHREADS) * 4;
        if (i4 < F2_USED) {
            float4 v = *reinterpret_cast<const float4*>(c0 + i4);
            float nxt = c0[i4 + 4];   // within F2_COPY buffer (zero-padded tail)
            *reinterpret_cast<float4*>(c1 + i4) = make_float4(v.y, v.z, v.w, nxt);
        }
    }
}

extern __shared__ float smem[];

__global__ __launch_bounds__(NTHREADS, 1)
void corr_kernel(const float* __restrict__ f1g,
                 const float* __restrict__ f2g,
                 float* __restrict__ out) {
    const int tid  = threadIdx.x;
    const int warp = tid >> 5;
    const int lane = tid & 31;
    const int hl   = warp & 3;      // h row (warp-uniform)
    const int dil  = warp >> 2;     // local di (warp-uniform)
    const int wg   = lane >> 1;     // w tile: w0 = wg*8
    const int djp  = lane & 1;      // dj parity
    const int w0   = wg * 8;

    const int b   = blockIdx.z;
    const int h0  = blockIdx.y * HB;
    const int di0 = blockIdx.x * DIB;
    const int r0  = h0 + di0 - PAD_;

    int rlo = (r0 < 0) ? -r0 : 0;
    int rhi = (r0 + NROW > H_) ? (H_ - r0) : NROW;
    if (rhi < rlo) { rlo = 0; rhi = 0; }
    const int nrows = rhi - rlo;

    float* buf0 = smem;
    float* buf1 = smem + BUF_FLOATS;

    // one-time zero of both f2 double-copies (padding/OOB stays zero forever)
    {
        float4 z = make_float4(0.f, 0.f, 0.f, 0.f);
        float4* z0 = reinterpret_cast<float4*>(buf0 + SMEM_F1);
        float4* z1 = reinterpret_cast<float4*>(buf1 + SMEM_F1);
        for (int i = tid; i < 2 * F2_COPY / 4; i += NTHREADS) { z0[i] = z; z1[i] = z; }
    }
    __syncthreads();

    // hoisted gmem bases (chunk stride is a constant add)
    const float* f1base = f1g + ((size_t)b * C_ * H_ + h0) * W_;
    const float* f2base = f2g + ((size_t)b * C_ * H_ + (r0 + 0)) * W_;
    const int chunk_gstride = CC * H_ * W_;   // floats per channel-chunk

    stage_chunk(f1base, f2base, buf0, rlo, nrows, tid);
    cp_commit();
    stage_chunk(f1base + chunk_gstride, f2base + chunk_gstride, buf1, rlo, nrows, tid);
    cp_commit();

    unsigned long long acc[11][4];
#pragma unroll
    for (int k = 0; k < 11; k++)
#pragma unroll
        for (int p = 0; p < 4; p++) acc[k][p] = 0ull;

    const int f1off = hl * F1_STRIDE + w0;
    const int f2off = SMEM_F1 + djp * F2_COPY + (hl + dil) * F2_STRIDE + w0;

    for (int cc = 0; cc < NCHUNK; cc++) {
        float* buf = (cc & 1) ? buf1 : buf0;
        if (cc < NCHUNK - 1) cp_wait<1>(); else cp_wait<0>();
        __syncthreads();                      // c0/f1 for chunk cc visible

        build_copy1(buf, tid);                // uniform across lanes, smem only
        __syncthreads();                      // copy1 visible

        compute_chunk(buf + f1off, buf + f2off, acc);

        __syncthreads();                      // all readers done with buf
        if (cc + 2 < NCHUNK)
            stage_chunk(f1base + (size_t)(cc + 2) * chunk_gstride,
                        f2base + (size_t)(cc + 2) * chunk_gstride,
                        buf, rlo, nrows, tid);
        cp_commit();
    }

    // ---- epilogue: rows dj = djp + 2k ----
    const float inv = 1.0f / 64.0f;
    const int di = di0 + dil;
    const int h  = h0 + hl;
    const int nk = (djp == 0) ? 11 : 10;   // dj=20 only exists for djp==0
    for (int k = 0; k < nk; k++) {
        const int d = di * KS_ + djp + 2 * k;
        float* o = out + (((size_t)b * (KS_ * KS_) + d) * H_ + h) * W_ + w0;
        float v[8];
#pragma unroll
        for (int p = 0; p < 4; p++) {
            float2 f = *reinterpret_cast<float2*>(&acc[k][p]);
            v[2 * p]     = f.x * inv;
            v[2 * p + 1] = f.y * inv;
        }
        *reinterpret_cast<float4*>(o)     = make_float4(v[0], v[1], v[2], v[3]);
        *reinterpret_cast<float4*>(o + 4) = make_float4(v[4], v[5], v[6], v[7]);
    }
}

extern "C" void kernel_launch(void* const* d_in, const int* in_sizes, int n_in,
                              void* d_out, int out_size) {
    const float* f1 = (const float*)d_in[0];
    const float* f2 = (const float*)d_in[1];
    float* out = (float*)d_out;

    cudaFuncSetAttribute(corr_kernel, cudaFuncAttributeMaxDynamicSharedMemorySize,
                         SMEM_BYTES);

    dim3 grid(KS_ / DIB, H_ / HB, B_);   // (7, 32, 4) = 896 CTAs
    corr_kernel<<<grid, NTHREADS, SMEM_BYTES>>>(f1, f2, out);
}

// round 8
// speedup vs baseline: 1.8067x; 1.1039x over previous
#include <cuda_runtime.h>
#include <cstdint>

// Correlation layer: out[b, di*21+dj, h, w] = (1/64) * sum_c f1[b,c,h,w] * f2pad[b,c,h+di,w+dj]
// B=4, C=64, H=W=128, MAX_DISP=10, KS=21 (441 displacements), fp32.

#define B_      4
#define C_      64
#define H_      128
#define W_      128
#define KS_     21
#define PAD_    10

#define HB   2      // h rows per CTA
#define DIB  3      // di values per CTA
#define CC   8      // channels per chunk
#define NCHUNK (C_ / CC)   // 8
#define PW   152    // padded f2 row width
#define NROW (HB + DIB - 1)  // 4

#define F1_STRIDE (CC * W_ + 4)   // 1028 floats (4112 B ≡ 16 mod 128)
#define F2_STRIDE (CC * PW + 4)   // 1220 floats (4880 B ≡ 16 mod 128)
#define SMEM_F1   (HB * F1_STRIDE)        // 2056 floats
#define F2_USED   (NROW * F2_STRIDE)      // 4880 floats
#define F2_COPY   (F2_USED + 12)          // 4892; copy1-copy0 = 19568 B ≡ 112 mod 128
                                          // (odd multiple of 16 -> conflict-free djp split)
#define BUF_FLOATS (SMEM_F1 + 2 * F2_COPY) // 11840 floats
#define SMEM_BYTES (2 * BUF_FLOATS * 4)    // 94720 B per CTA (2 CTAs/SM)

#define NTHREADS 192   // 6 warps = 2 hl * 3 dil; lanes = 16 wg * 2 djp

// ---------------- cp.async helpers ----------------
__device__ __forceinline__ void cp_async16(float* smem_dst, const float* gsrc) {
    uint32_t s = (uint32_t)__cvta_generic_to_shared(smem_dst);
    asm volatile("cp.async.cg.shared.global [%0], [%1], 16;\n" :: "r"(s), "l"(gsrc));
}
__device__ __forceinline__ void cp_async8(float* smem_dst, const float* gsrc) {
    uint32_t s = (uint32_t)__cvta_generic_to_shared(smem_dst);
    asm volatile("cp.async.ca.shared.global [%0], [%1], 8;\n" :: "r"(s), "l"(gsrc));
}
__device__ __forceinline__ void cp_commit() {
    asm volatile("cp.async.commit_group;\n" ::: "memory");
}
template <int N>
__device__ __forceinline__ void cp_wait() {
    asm volatile("cp.async.wait_group %0;\n" :: "n"(N) : "memory");
}

// packed f32x2 fma: d = a*b + c on both 32-bit halves
__device__ __forceinline__ unsigned long long fma_x2(unsigned long long a,
                                                     unsigned long long b,
                                                     unsigned long long c) {
    unsigned long long d;
    asm("fma.rn.f32x2 %0, %1, %2, %3;" : "=l"(d) : "l"(a), "l"(b), "l"(c));
    return d;
}

// ---------------- inner compute ----------------
// Thread: dj = djp + 2k (k=0..10; k=10 junk for djp=1, never stored),
// w in [w0, w0+8). f2p points at copy_djp; copy1 is c0 shifted by one float,
// so both parities read identical even packed offsets: fb2[k+p].
__device__ __forceinline__ void compute_chunk(const float* __restrict__ f1p,
                                              const float* __restrict__ f2p,
                                              unsigned long long (&acc)[11][4]) {
#pragma unroll
    for (int c = 0; c < CC; c++) {
        const ulonglong2* f1v = reinterpret_cast<const ulonglong2*>(f1p + c * W_);
        const ulonglong2* f2v = reinterpret_cast<const ulonglong2*>(f2p + c * PW);
        unsigned long long fa2[4];
        unsigned long long fb2[14];
#pragma unroll
        for (int i = 0; i < 2; i++) {
            ulonglong2 t = f1v[i];
            fa2[2 * i] = t.x; fa2[2 * i + 1] = t.y;
        }
#pragma unroll
        for (int i = 0; i < 7; i++) {
            ulonglong2 t = f2v[i];
            fb2[2 * i] = t.x; fb2[2 * i + 1] = t.y;
        }
#pragma unroll
        for (int k = 0; k < 11; k++) {
#pragma unroll
            for (int p = 0; p < 4; p++)
                acc[k][p] = fma_x2(fa2[p], fb2[k + p], acc[k][p]);
        }
    }
}

// ---------------- staging (cp.async, gmem -> smem) ----------------
// f1: HB x CC x 128 floats via 16B. c0: interior x in [10,138) via 8B.
// copy1 is built in smem afterwards (never staged from gmem).
// 192 ≡ 0 mod 64: per-thread x components are loop-invariant.
__device__ __forceinline__ void stage_chunk(const float* __restrict__ f1base,
                                            const float* __restrict__ f2base,
                                            float* buf,
                                            int rlo, int nrows, int tid) {
    // ---- f1: items i = hc*32 + w4, hc = h*8 + c, 512 total ----
    {
        const int w4 = tid & 31;                // invariant
        int hc = tid >> 5;                      // advances by 6
        float* f1b = buf + w4 * 4;
        const float* src0 = f1base + w4 * 4;
#pragma unroll
        for (int j = 0; j < 3; j++) {
            if (hc < HB * CC) {
                int h = hc >> 3, c = hc & 7;
                cp_async16(f1b + h * F1_STRIDE + c * W_,
                           src0 + c * (H_ * W_) + h * W_);
            }
            hc += 6;
        }
    }
    // ---- c0: items i = (r*8 + c)*64 + x2, nrows*512 total ----
    {
        const int x2 = tid & 63;                // invariant
        int rc = tid >> 6;                      // r*8 + c, advances by 3
        const int rcmax = nrows * 8;
        float* c0 = buf + SMEM_F1 + rlo * F2_STRIDE + PAD_ + x2 * 2;
        const float* src0 = f2base + rlo * W_ + x2 * 2;
#pragma unroll
        for (int j = 0; j < 11; j++) {
            if (rc < rcmax) {
                int r = rc >> 3, c = rc & 7;
                cp_async8(c0 + r * F2_STRIDE + c * PW,
                          src0 + c * (H_ * W_) + r * W_);
            }
            rc += 3;
        }
    }
}

// ---------------- copy1 build (smem -> smem 1-float shift) ----------------
// copy1[i] = c0[i+1]; covers all of F2_USED (tail read stays in zero padding).
__device__ __forceinline__ void build_copy1(float* buf, int tid) {
    const float* c0 = buf + SMEM_F1;
    float* c1 = buf + SMEM_F1 + F2_COPY;
#pragma unroll
    for (int j = 0; j < (F2_USED / 4 + NTHREADS - 1) / NTHREADS; j++) {  // 7 iters
        int i4 = (tid + j * NTHREADS) * 4;
        if (i4 < F2_USED) {
            float4 v = *reinterpret_cast<const float4*>(c0 + i4);
            float nxt = c0[i4 + 4];
            *reinterpret_cast<float4*>(c1 + i4) = make_float4(v.y, v.z, v.w, nxt);
        }
    }
}

extern __shared__ float smem[];

__global__ __launch_bounds__(NTHREADS, 2)
void corr_kernel(const float* __restrict__ f1g,
                 const float* __restrict__ f2g,
                 float* __restrict__ out) {
    const int tid  = threadIdx.x;
    const int warp = tid >> 5;
    const int lane = tid & 31;
    const int hl   = warp & 1;      // h row (warp-uniform), HB=2
    const int dil  = warp >> 1;     // local di (warp-uniform), 0..2
    const int wg   = lane >> 1;     // w tile: w0 = wg*8
    const int djp  = lane & 1;      // dj parity
    const int w0   = wg * 8;

    const int b   = blockIdx.z;
    const int h0  = blockIdx.y * HB;
    const int di0 = blockIdx.x * DIB;
    const int r0  = h0 + di0 - PAD_;

    int rlo = (r0 < 0) ? -r0 : 0;
    int rhi = (r0 + NROW > H_) ? (H_ - r0) : NROW;
    if (rhi < rlo) { rlo = 0; rhi = 0; }
    const int nrows = rhi - rlo;

    float* buf0 = smem;
    float* buf1 = smem + BUF_FLOATS;

    // one-time zero of both f2 double-copies (padding/OOB stays zero forever)
    {
        float4 z = make_float4(0.f, 0.f, 0.f, 0.f);
        float4* z0 = reinterpret_cast<float4*>(buf0 + SMEM_F1);
        float4* z1 = reinterpret_cast<float4*>(buf1 + SMEM_F1);
        for (int i = tid; i < 2 * F2_COPY / 4; i += NTHREADS) { z0[i] = z; z1[i] = z; }
    }
    __syncthreads();

    // hoisted gmem bases (chunk stride is a constant add)
    const float* f1base = f1g + ((size_t)b * C_ * H_ + h0) * W_;
    const float* f2base = f2g + ((size_t)b * C_ * H_ + r0) * W_;
    const int chunk_gstride = CC * H_ * W_;

    stage_chunk(f1base, f2base, buf0, rlo, nrows, tid);
    cp_commit();
    stage_chunk(f1base + chunk_gstride, f2base + chunk_gstride, buf1, rlo, nrows, tid);
    cp_commit();

    // prologue: chunk 0 staged -> build its copy1
    cp_wait<1>();
    __syncthreads();          // c0[0] visible to all
    build_copy1(buf0, tid);   // c1[0]; visibility covered by sync #1 of iter 0

    unsigned long long acc[11][4];
#pragma unroll
    for (int k = 0; k < 11; k++)
#pragma unroll
        for (int p = 0; p < 4; p++) acc[k][p] = 0ull;

    const int f1off = hl * F1_STRIDE + w0;
    const int f2off = SMEM_F1 + djp * F2_COPY + (hl + dil) * F2_STRIDE + w0;

    for (int cc = 0; cc < NCHUNK; cc++) {
        float* buf  = (cc & 1) ? buf1 : buf0;
        float* nbuf = (cc & 1) ? buf0 : buf1;

        if (cc < NCHUNK - 1) cp_wait<0>();   // all staged groups (incl cc+1) done
        __syncthreads();                     // c0[cc+1] + c1[cc] visible to all

        if (cc + 1 < NCHUNK) build_copy1(nbuf, tid);  // overlaps others' compute
        compute_chunk(buf + f1off, buf + f2off, acc);

        __syncthreads();                     // readers of buf done; c1[cc+1] built
        if (cc + 2 < NCHUNK) {
            stage_chunk(f1base + (size_t)(cc + 2) * chunk_gstride,
                        f2base + (size_t)(cc + 2) * chunk_gstride,
                        buf, rlo, nrows, tid);
            cp_commit();
        }
    }

    // ---- epilogue: rows dj = djp + 2k ----
    const float inv = 1.0f / 64.0f;
    const int di = di0 + dil;
    const int h  = h0 + hl;
    const int nk = (djp == 0) ? 11 : 10;   // dj=20 only exists for djp==0
    for (int k = 0; k < nk; k++) {
        const int d = di * KS_ + djp + 2 * k;
        float* o = out + (((size_t)b * (KS_ * KS_) + d) * H_ + h) * W_ + w0;
        float v[8];
#pragma unroll
        for (int p = 0; p < 4; p++) {
            float2 f = *reinterpret_cast<float2*>(&acc[k][p]);
            v[2 * p]     = f.x * inv;
            v[2 * p + 1] = f.y * inv;
        }
        *reinterpret_cast<float4*>(o)     = make_float4(v[0], v[1], v[2], v[3]);
        *reinterpret_cast<float4*>(o + 4) = make_float4(v[4], v[5], v[6], v[7]);
    }
}

extern "C" void kernel_launch(void* const* d_in, const int* in_sizes, int n_in,
                              void* d_out, int out_size) {
    const float* f1 = (const float*)d_in[0];
    const float* f2 = (const float*)d_in[1];
    float* out = (float*)d_out;

    cudaFuncSetAttribute(corr_kernel, cudaFuncAttributeMaxDynamicSharedMemorySize,
                         SMEM_BYTES);

    dim3 grid(KS_ / DIB, H_ / HB, B_);   // (7, 64, 4) = 1792 CTAs
    corr_kernel<<<grid, NTHREADS, SMEM_BYTES>>>(f1, f2, out);
}

// round 9
// speedup vs baseline: 1.8077x; 1.0005x over previous
#include <cuda_runtime.h>
#include <cstdint>

// Correlation layer: out[b, di*21+dj, h, w] = (1/64) * sum_c f1[b,c,h,w] * f2pad[b,c,h+di,w+dj]
// B=4, C=64, H=W=128, MAX_DISP=10, KS=21 (441 displacements), fp32.

#define B_      4
#define C_      64
#define H_      128
#define W_      128
#define KS_     21
#define PAD_    10

#define HB   2      // h rows per CTA
#define DIB  3      // di values per CTA
#define CC   8      // channels per chunk
#define NCHUNK (C_ / CC)   // 8
#define PW   152    // padded f2 row width
#define NROW (HB + DIB - 1)  // 4

#define F1_STRIDE (CC * W_ + 4)   // 1028 floats (4112 B ≡ 16 mod 128)
#define F2_STRIDE (CC * PW + 4)   // 1220 floats (4880 B ≡ 16 mod 128)
#define SMEM_F1   (HB * F1_STRIDE)        // 2056 floats
#define F2_USED   (NROW * F2_STRIDE)      // 4880 floats
#define F2_COPY   (F2_USED + 12)          // 4892; copy1-copy0 = 19568 B ≡ 112 mod 128
                                          // (odd multiple of 16 -> conflict-free djp split)
#define BUF_FLOATS (SMEM_F1 + 2 * F2_COPY) // 11840 floats
#define SMEM_BYTES (2 * BUF_FLOATS * 4)    // 94720 B per CTA (2 CTAs/SM)

#define NTHREADS 192   // 6 warps = 2 hl * 3 dil; lanes = 16 wg * 2 djp

// ---------------- cp.async helpers ----------------
__device__ __forceinline__ void cp_async16(float* smem_dst, const float* gsrc) {
    uint32_t s = (uint32_t)__cvta_generic_to_shared(smem_dst);
    asm volatile("cp.async.cg.shared.global [%0], [%1], 16;\n" :: "r"(s), "l"(gsrc));
}
__device__ __forceinline__ void cp_async8(float* smem_dst, const float* gsrc) {
    uint32_t s = (uint32_t)__cvta_generic_to_shared(smem_dst);
    asm volatile("cp.async.ca.shared.global [%0], [%1], 8;\n" :: "r"(s), "l"(gsrc));
}
__device__ __forceinline__ void cp_commit() {
    asm volatile("cp.async.commit_group;\n" ::: "memory");
}
template <int N>
__device__ __forceinline__ void cp_wait() {
    asm volatile("cp.async.wait_group %0;\n" :: "n"(N) : "memory");
}

// packed f32x2 fma: d = a*b + c on both 32-bit halves
__device__ __forceinline__ unsigned long long fma_x2(unsigned long long a,
                                                     unsigned long long b,
                                                     unsigned long long c) {
    unsigned long long d;
    asm("fma.rn.f32x2 %0, %1, %2, %3;" : "=l"(d) : "l"(a), "l"(b), "l"(c));
    return d;
}

// ---------------- inner compute ----------------
// Thread: dj = djp + 2k (k=0..10; k=10 junk for djp=1, never stored),
// w in [w0, w0+8). f2p points at copy_djp; copy1 is c0 shifted by one float,
// so both parities read identical even packed offsets: fb2[k+p].
__device__ __forceinline__ void compute_chunk(const float* __restrict__ f1p,
                                              const float* __restrict__ f2p,
                                              unsigned long long (&acc)[11][4]) {
#pragma unroll
    for (int c = 0; c < CC; c++) {
        const ulonglong2* f1v = reinterpret_cast<const ulonglong2*>(f1p + c * W_);
        const ulonglong2* f2v = reinterpret_cast<const ulonglong2*>(f2p + c * PW);
        unsigned long long fa2[4];
        unsigned long long fb2[14];
#pragma unroll
        for (int i = 0; i < 2; i++) {
            ulonglong2 t = f1v[i];
            fa2[2 * i] = t.x; fa2[2 * i + 1] = t.y;
        }
#pragma unroll
        for (int i = 0; i < 7; i++) {
            ulonglong2 t = f2v[i];
            fb2[2 * i] = t.x; fb2[2 * i + 1] = t.y;
        }
#pragma unroll
        for (int k = 0; k < 11; k++) {
#pragma unroll
            for (int p = 0; p < 4; p++)
                acc[k][p] = fma_x2(fa2[p], fb2[k + p], acc[k][p]);
        }
    }
}

// ---------------- staging (cp.async, gmem -> smem) ----------------
// f1: HB x CC x 128 floats via 16B. c0: interior x in [10,138) via 8B.
// copy1 is built in smem afterwards (never staged from gmem).
// 192 ≡ 0 mod 64: per-thread x components are loop-invariant.
__device__ __forceinline__ void stage_chunk(const float* __restrict__ f1base,
                                            const float* __restrict__ f2base,
                                            float* buf,
                                            int rlo, int nrows, int tid) {
    // ---- f1: items i = hc*32 + w4, hc = h*8 + c, 512 total ----
    {
        const int w4 = tid & 31;                // invariant
        int hc = tid >> 5;                      // advances by 6
        float* f1b = buf + w4 * 4;
        const float* src0 = f1base + w4 * 4;
#pragma unroll
        for (int j = 0; j < 3; j++) {
            if (hc < HB * CC) {
                int h = hc >> 3, c = hc & 7;
                cp_async16(f1b + h * F1_STRIDE + c * W_,
                           src0 + c * (H_ * W_) + h * W_);
            }
            hc += 6;
        }
    }
    // ---- c0: items i = (r*8 + c)*64 + x2, nrows*512 total ----
    {
        const int x2 = tid & 63;                // invariant
        int rc = tid >> 6;                      // r*8 + c, advances by 3
        const int rcmax = nrows * 8;
        float* c0 = buf + SMEM_F1 + rlo * F2_STRIDE + PAD_ + x2 * 2;
        const float* src0 = f2base + rlo * W_ + x2 * 2;
#pragma unroll
        for (int j = 0; j < 11; j++) {
            if (rc < rcmax) {
                int r = rc >> 3, c = rc & 7;
                cp_async8(c0 + r * F2_STRIDE + c * PW,
                          src0 + c * (H_ * W_) + r * W_);
            }
            rc += 3;
        }
    }
}

// ---------------- copy1 build (smem -> smem 1-float shift) ----------------
// copy1[i] = c0[i+1]; covers all of F2_USED (tail read stays in zero padding).
__device__ __forceinline__ void build_copy1(float* buf, int tid) {
    const float* c0 = buf + SMEM_F1;
    float* c1 = buf + SMEM_F1 + F2_COPY;
#pragma unroll
    for (int j = 0; j < (F2_USED / 4 + NTHREADS - 1) / NTHREADS; j++) {  // 7 iters
        int i4 = (tid + j * NTHREADS) * 4;
        if (i4 < F2_USED) {
            float4 v = *reinterpret_cast<const float4*>(c0 + i4);
            float nxt = c0[i4 + 4];
            *reinterpret_cast<float4*>(c1 + i4) = make_float4(v.y, v.z, v.w, nxt);
        }
    }
}

extern __shared__ float smem[];

__global__ __launch_bounds__(NTHREADS, 2)
void corr_kernel(const float* __restrict__ f1g,
                 const float* __restrict__ f2g,
                 float* __restrict__ out) {
    const int tid  = threadIdx.x;
    const int warp = tid >> 5;
    const int lane = tid & 31;
    const int hl   = warp & 1;      // h row (warp-uniform), HB=2
    const int dil  = warp >> 1;     // local di (warp-uniform), 0..2
    const int wg   = lane >> 1;     // w tile: w0 = wg*8
    const int djp  = lane & 1;      // dj parity
    const int w0   = wg * 8;

    const int b   = blockIdx.z;
    const int h0  = blockIdx.y * HB;
    const int di0 = blockIdx.x * DIB;
    const int r0  = h0 + di0 - PAD_;

    int rlo = (r0 < 0) ? -r0 : 0;
    int rhi = (r0 + NROW > H_) ? (H_ - r0) : NROW;
    if (rhi < rlo) { rlo = 0; rhi = 0; }
    const int nrows = rhi - rlo;

    float* buf0 = smem;
    float* buf1 = smem + BUF_FLOATS;

    // one-time zero of both f2 double-copies (padding/OOB stays zero forever)
    {
        float4 z = make_float4(0.f, 0.f, 0.f, 0.f);
        float4* z0 = reinterpret_cast<float4*>(buf0 + SMEM_F1);
        float4* z1 = reinterpret_cast<float4*>(buf1 + SMEM_F1);
        for (int i = tid; i < 2 * F2_COPY / 4; i += NTHREADS) { z0[i] = z; z1[i] = z; }
    }
    __syncthreads();

    // hoisted gmem bases (chunk stride is a constant add)
    const float* f1base = f1g + ((size_t)b * C_ * H_ + h0) * W_;
    const float* f2base = f2g + ((size_t)b * C_ * H_ + r0) * W_;
    const int chunk_gstride = CC * H_ * W_;

    stage_chunk(f1base, f2base, buf0, rlo, nrows, tid);
    cp_commit();
    stage_chunk(f1base + chunk_gstride, f2base + chunk_gstride, buf1, rlo, nrows, tid);
    cp_commit();

    // prologue: chunk 0 staged -> build its copy1
    cp_wait<1>();
    __syncthreads();          // c0[0] visible to all
    build_copy1(buf0, tid);   // c1[0]; visibility covered by sync #1 of iter 0

    unsigned long long acc[11][4];
#pragma unroll
    for (int k = 0; k < 11; k++)
#pragma unroll
        for (int p = 0; p < 4; p++) acc[k][p] = 0ull;

    const int f1off = hl * F1_STRIDE + w0;
    const int f2off = SMEM_F1 + djp * F2_COPY + (hl + dil) * F2_STRIDE + w0;

    for (int cc = 0; cc < NCHUNK; cc++) {
        float* buf  = (cc & 1) ? buf1 : buf0;
        float* nbuf = (cc & 1) ? buf0 : buf1;

        if (cc < NCHUNK - 1) cp_wait<0>();   // all staged groups (incl cc+1) done
        __syncthreads();                     // c0[cc+1] + c1[cc] visible to all

        if (cc + 1 < NCHUNK) build_copy1(nbuf, tid);  // overlaps others' compute
        compute_chunk(buf + f1off, buf + f2off, acc);

        __syncthreads();                     // readers of buf done; c1[cc+1] built
        if (cc + 2 < NCHUNK) {
            stage_chunk(f1base + (size_t)(cc + 2) * chunk_gstride,
                        f2base + (size_t)(cc + 2) * chunk_gstride,
                        buf, rlo, nrows, tid);
            cp_commit();
        }
    }

    // ---- epilogue: rows dj = djp + 2k ----
    const float inv = 1.0f / 64.0f;
    const int di = di0 + dil;
    const int h  = h0 + hl;
    const int nk = (djp == 0) ? 11 : 10;   // dj=20 only exists for djp==0
    for (int k = 0; k < nk; k++) {
        const int d = di * KS_ + djp + 2 * k;
        float* o = out + (((size_t)b * (KS_ * KS_) + d) * H_ + h) * W_ + w0;
        float v[8];
#pragma unroll
        for (int p = 0; p < 4; p++) {
            float2 f = *reinterpret_cast<float2*>(&acc[k][p]);
            v[2 * p]     = f.x * inv;
            v[2 * p + 1] = f.y * inv;
        }
        *reinterpret_cast<float4*>(o)     = make_float4(v[0], v[1], v[2], v[3]);
        *reinterpret_cast<float4*>(o + 4) = make_float4(v[4], v[5], v[6], v[7]);
    }
}

extern "C" void kernel_launch(void* const* d_in, const int* in_sizes, int n_in,
                              void* d_out, int out_size) {
    const float* f1 = (const float*)d_in[0];
    const float* f2 = (const float*)d_in[1];
    float* out = (float*)d_out;

    cudaFuncSetAttribute(corr_kernel, cudaFuncAttributeMaxDynamicSharedMemorySize,
                         SMEM_BYTES);

    dim3 grid(KS_ / DIB, H_ / HB, B_);   // (7, 64, 4) = 1792 CTAs
    corr_kernel<<<grid, NTHREADS, SMEM_BYTES>>>(f1, f2, out);
}